// round 6
// baseline (speedup 1.0000x reference)
#include <cuda_runtime.h>
#include <cuda_bf16.h>
#include <math.h>

// Sticky device flag: set to 1 if the structural assumption (flat = p*stride,
// p < P) is violated. Inputs are fixed for the whole run, so the flag value is
// identical on every replay -> deterministic work per replay.
__device__ int g_mismatch = 0;

// Fused zero-fill + scatter exploiting flat = p*stride (p < P) structure.
// Each thread writes one float4 (4 consecutive columns). stride is a multiple
// of 4, so at most the FIRST column of the group can be a pair position.
// Verifies src/dst for every pair it places; mismatch -> g_mismatch = 1.
__global__ void fused_fill_scatter_kernel(const int* __restrict__ path_src,
                                          const int* __restrict__ path_dst,
                                          const int* __restrict__ path_len,
                                          const float* __restrict__ b,
                                          float4* __restrict__ out,
                                          int n_vec4, int row_vec4, int n,
                                          int stride, int P, int maxpd) {
    int v = blockIdx.x * blockDim.x + threadIdx.x;
    if (v >= n_vec4) return;

    int r = v / row_vec4;                 // row (32-bit div; n_vec4 < 2^31)
    int c = (v - r * row_vec4) << 2;      // first column of this float4 group

    float4 val = make_float4(0.f, 0.f, 0.f, 0.f);
    if (c % stride == 0) {
        int p = (r * n + c) / stride;     // r*n + c <= n*n-1 < 2^31
        if (p < P) {
            int L = __ldg(&path_len[p]);
            if (L > 0) {
                int idx = (L < maxpd ? L : maxpd) - 1;
                val.x = __ldg(&b[idx]);
            }
            if (__ldg(&path_src[p]) != r || __ldg(&path_dst[p]) != c) {
                g_mismatch = 1;
            }
        }
    }
    out[v] = val;
}

// ---- Fallback / repair path ----

__global__ void zero_fill_kernel(float4* __restrict__ out, long long n_vec4,
                                 int only_if_mismatch) {
    if (only_if_mismatch && g_mismatch == 0) return;
    long long i = (long long)blockIdx.x * blockDim.x + threadIdx.x;
    if (i < n_vec4) {
        out[i] = make_float4(0.f, 0.f, 0.f, 0.f);
    }
}

__global__ void scatter_kernel(const int* __restrict__ path_src,
                               const int* __restrict__ path_dst,
                               const int* __restrict__ path_len,
                               const float* __restrict__ b,
                               float* __restrict__ out,
                               int P, long long n, int maxpd,
                               int only_if_mismatch) {
    if (only_if_mismatch && g_mismatch == 0) return;
    int i = blockIdx.x * blockDim.x + threadIdx.x;
    if (i >= P) return;
    int len = path_len[i];
    float v = 0.0f;
    if (len > 0) {
        int idx = (len < maxpd ? len : maxpd) - 1;
        if (idx < 0) idx = 0;
        v = __ldg(&b[idx]);
    }
    long long flat = (long long)path_src[i] * n + (long long)path_dst[i];
    out[flat] = v;
}

extern "C" void kernel_launch(void* const* d_in, const int* in_sizes, int n_in,
                              void* d_out, int out_size) {
    // metadata order: x (float32, N*D), b (float32, MAX_PATH),
    //                 path_src (int32, P), path_dst (int32, P), path_len (int32, P)
    const float* b        = (const float*)d_in[1];
    const int*   path_src = (const int*)d_in[2];
    const int*   path_dst = (const int*)d_in[3];
    const int*   path_len = (const int*)d_in[4];
    float* out = (float*)d_out;

    const int maxpd = in_sizes[1];
    const int P     = in_sizes[2];

    long long total = (long long)out_size;
    long long n_ll  = (long long)llround(sqrt((double)total));
    int n = (int)n_ll;

    const int threads = 256;
    long long n_vec4 = total / 4;
    long long fill_blocks = (n_vec4 + threads - 1) / threads;
    int scatter_blocks = (P + threads - 1) / threads;

    // Structural feasibility. stride is the FLOOR of total/P (matches the
    // reference's (N*N)//P); pairs occupy flat = p*stride for p < P, the tail
    // of the matrix is all zeros (handled by the p < P guard in the kernel).
    long long stride_ll = (P > 0) ? (total / P) : 0;
    bool structured = (P > 0) && (stride_ll >= 4) && (stride_ll % 4 == 0) &&
                      (n > 0) && ((long long)n * n == total) &&
                      (n % (int)stride_ll == 0) && ((n & 3) == 0) &&
                      (total / 4 <= 0x7fffffffLL);

    if (structured) {
        int stride = (int)stride_ll;
        fused_fill_scatter_kernel<<<(unsigned int)fill_blocks, threads>>>(
            path_src, path_dst, path_len, b, (float4*)out,
            (int)n_vec4, n >> 2, n, stride, P, maxpd);
        // Repair path: no-ops unless a mismatch was ever detected.
        zero_fill_kernel<<<(unsigned int)fill_blocks, threads>>>(
            (float4*)out, n_vec4, /*only_if_mismatch=*/1);
        scatter_kernel<<<scatter_blocks, threads>>>(
            path_src, path_dst, path_len, b, out, P, n_ll, maxpd,
            /*only_if_mismatch=*/1);
    } else {
        // General path: unconditional zero + scatter.
        zero_fill_kernel<<<(unsigned int)fill_blocks, threads>>>(
            (float4*)out, n_vec4, /*only_if_mismatch=*/0);
        scatter_kernel<<<scatter_blocks, threads>>>(
            path_src, path_dst, path_len, b, out, P, n_ll, maxpd,
            /*only_if_mismatch=*/0);
    }
}

// round 7
// speedup vs baseline: 1.1014x; 1.1014x over previous
#include <cuda_runtime.h>
#include <cuda_bf16.h>
#include <math.h>

// Sticky device flag: set to 1 if the structural assumption (flat = p*stride,
// p < P) is violated. Inputs are fixed for the whole run, so the flag value is
// identical on every replay -> deterministic work per replay.
__device__ int g_mismatch = 0;

// Fused zero-fill + scatter exploiting flat = p*stride (p < P) structure with
// all-power-of-two shapes: pure shift/mask addressing, one float4 store per
// thread. Verifies src/dst for every pair it places.
__global__ void fused_fill_scatter_pow2_kernel(
        const int* __restrict__ path_src,
        const int* __restrict__ path_dst,
        const int* __restrict__ path_len,
        const float* __restrict__ b,
        float4* __restrict__ out,
        int n_vec4,
        int sv_mask,     // (stride/4) - 1 : which float4 groups hold a pair
        int sv_shift,    // log2(stride/4) : v -> pair id
        int n_shift,     // log2(n)        : flat -> row
        int n_mask,      // n - 1          : flat -> col
        int P, int maxpd) {
    int v = blockIdx.x * blockDim.x + threadIdx.x;
    if (v >= n_vec4) return;

    float4 val = make_float4(0.f, 0.f, 0.f, 0.f);
    if ((v & sv_mask) == 0) {
        int p = v >> sv_shift;
        if (p < P) {
            int L = __ldg(&path_len[p]);
            if (L > 0) {
                int idx = (L < maxpd ? L : maxpd) - 1;
                val.x = __ldg(&b[idx]);
            }
            int flat = v << 2;
            int r = flat >> n_shift;
            int c = flat & n_mask;
            if (__ldg(&path_src[p]) != r || __ldg(&path_dst[p]) != c) {
                g_mismatch = 1;
            }
        }
    }
    out[v] = val;
}

// ---- Fallback / repair path ----

__global__ void zero_fill_kernel(float4* __restrict__ out, long long n_vec4,
                                 int only_if_mismatch) {
    if (only_if_mismatch && g_mismatch == 0) return;
    long long i = (long long)blockIdx.x * blockDim.x + threadIdx.x;
    if (i < n_vec4) {
        out[i] = make_float4(0.f, 0.f, 0.f, 0.f);
    }
}

__global__ void scatter_kernel(const int* __restrict__ path_src,
                               const int* __restrict__ path_dst,
                               const int* __restrict__ path_len,
                               const float* __restrict__ b,
                               float* __restrict__ out,
                               int P, long long n, int maxpd,
                               int only_if_mismatch) {
    if (only_if_mismatch && g_mismatch == 0) return;
    int i = blockIdx.x * blockDim.x + threadIdx.x;
    if (i >= P) return;
    int len = path_len[i];
    float v = 0.0f;
    if (len > 0) {
        int idx = (len < maxpd ? len : maxpd) - 1;
        if (idx < 0) idx = 0;
        v = __ldg(&b[idx]);
    }
    long long flat = (long long)path_src[i] * n + (long long)path_dst[i];
    out[flat] = v;
}

static inline bool is_pow2_ll(long long x) { return x > 0 && (x & (x - 1)) == 0; }
static inline int log2_ll(long long x) {
    int s = 0;
    while ((1LL << s) < x) s++;
    return s;
}

extern "C" void kernel_launch(void* const* d_in, const int* in_sizes, int n_in,
                              void* d_out, int out_size) {
    // metadata order: x (float32, N*D), b (float32, MAX_PATH),
    //                 path_src (int32, P), path_dst (int32, P), path_len (int32, P)
    const float* b        = (const float*)d_in[1];
    const int*   path_src = (const int*)d_in[2];
    const int*   path_dst = (const int*)d_in[3];
    const int*   path_len = (const int*)d_in[4];
    float* out = (float*)d_out;

    const int maxpd = in_sizes[1];
    const int P     = in_sizes[2];

    long long total = (long long)out_size;
    long long n_ll  = (long long)llround(sqrt((double)total));
    int n = (int)n_ll;

    const int threads = 256;
    long long n_vec4 = total / 4;
    long long fill_blocks = (n_vec4 + threads - 1) / threads;
    int scatter_blocks = (P + threads - 1) / threads;

    // Structural feasibility: stride = floor(total/P) (matches (N*N)//P in the
    // reference); pairs at flat = p*stride for p < P, tail all zeros. Require
    // power-of-two n and stride so the kernel is pure shift/mask.
    long long stride_ll = (P > 0) ? (total / P) : 0;
    bool structured = (P > 0) && (stride_ll >= 4) && (stride_ll % 4 == 0) &&
                      (n > 0) && ((long long)n * n == total) &&
                      is_pow2_ll(n_ll) && is_pow2_ll(stride_ll) &&
                      (total / 4 <= 0x7fffffffLL);

    if (structured) {
        long long sv = stride_ll / 4;     // float4 groups per pair slot (pow2)
        int sv_shift = log2_ll(sv);
        int n_shift  = log2_ll(n_ll);
        fused_fill_scatter_pow2_kernel<<<(unsigned int)fill_blocks, threads>>>(
            path_src, path_dst, path_len, b, (float4*)out,
            (int)n_vec4, (int)(sv - 1), sv_shift, n_shift, n - 1, P, maxpd);
        // Repair path: no-ops unless a mismatch was ever detected.
        zero_fill_kernel<<<(unsigned int)fill_blocks, threads>>>(
            (float4*)out, n_vec4, /*only_if_mismatch=*/1);
        scatter_kernel<<<scatter_blocks, threads>>>(
            path_src, path_dst, path_len, b, out, P, n_ll, maxpd,
            /*only_if_mismatch=*/1);
    } else {
        // General path: unconditional zero + scatter.
        zero_fill_kernel<<<(unsigned int)fill_blocks, threads>>>(
            (float4*)out, n_vec4, /*only_if_mismatch=*/0);
        scatter_kernel<<<scatter_blocks, threads>>>(
            path_src, path_dst, path_len, b, out, P, n_ll, maxpd,
            /*only_if_mismatch=*/0);
    }
}

// round 8
// speedup vs baseline: 1.1202x; 1.0170x over previous
#include <cuda_runtime.h>
#include <cuda_bf16.h>
#include <math.h>

// Sticky device flag: set to 1 if the structural assumption (flat = p*stride,
// p < P) is violated. Inputs are fixed for the whole run, so the flag value is
// identical on every replay -> deterministic work per replay.
__device__ int g_mismatch = 0;

#define GROUPS_PER_THREAD 4

// Fused zero-fill + scatter exploiting flat = p*stride (p < P) structure with
// all-power-of-two shapes. Each thread handles 4 float4 groups: ALL loads are
// issued first (4 independent len->b chains, MLP=4), then 4 coalesced
// STG.128. Verifies src/dst for every pair it places.
__global__ void fused_fill_scatter_pow2_kernel(
        const int* __restrict__ path_src,
        const int* __restrict__ path_dst,
        const int* __restrict__ path_len,
        const float* __restrict__ b,
        float4* __restrict__ out,
        int n_vec4,
        int sv_mask,     // (stride/4) - 1 : which float4 groups hold a pair
        int sv_shift,    // log2(stride/4) : group -> pair id
        int n_shift,     // log2(n)        : flat -> row
        int n_mask,      // n - 1          : flat -> col
        int P, int maxpd) {
    int base = blockIdx.x * (blockDim.x * GROUPS_PER_THREAD) + threadIdx.x;

    float vx[GROUPS_PER_THREAD];
    int mism = 0;

    // Phase 1: all loads (independent chains; verify loads don't gate stores)
#pragma unroll
    for (int i = 0; i < GROUPS_PER_THREAD; i++) {
        int g = base + i * blockDim.x;
        vx[i] = 0.0f;
        if (g < n_vec4 && (g & sv_mask) == 0) {
            int p = g >> sv_shift;
            if (p < P) {
                int L = __ldg(&path_len[p]);
                if (L > 0) {
                    int idx = (L < maxpd ? L : maxpd) - 1;
                    vx[i] = __ldg(&b[idx]);
                }
                int flat = g << 2;
                int r = flat >> n_shift;
                int c = flat & n_mask;
                if (__ldg(&path_src[p]) != r || __ldg(&path_dst[p]) != c) {
                    mism = 1;
                }
            }
        }
    }
    if (mism) g_mismatch = 1;

    // Phase 2: coalesced stores
#pragma unroll
    for (int i = 0; i < GROUPS_PER_THREAD; i++) {
        int g = base + i * blockDim.x;
        if (g < n_vec4) {
            out[g] = make_float4(vx[i], 0.f, 0.f, 0.f);
        }
    }
}

// ---- Fallback / repair path ----

__global__ void zero_fill_kernel(float4* __restrict__ out, long long n_vec4,
                                 int only_if_mismatch) {
    if (only_if_mismatch && g_mismatch == 0) return;
    long long i = (long long)blockIdx.x * blockDim.x + threadIdx.x;
    if (i < n_vec4) {
        out[i] = make_float4(0.f, 0.f, 0.f, 0.f);
    }
}

__global__ void scatter_kernel(const int* __restrict__ path_src,
                               const int* __restrict__ path_dst,
                               const int* __restrict__ path_len,
                               const float* __restrict__ b,
                               float* __restrict__ out,
                               int P, long long n, int maxpd,
                               int only_if_mismatch) {
    if (only_if_mismatch && g_mismatch == 0) return;
    int i = blockIdx.x * blockDim.x + threadIdx.x;
    if (i >= P) return;
    int len = path_len[i];
    float v = 0.0f;
    if (len > 0) {
        int idx = (len < maxpd ? len : maxpd) - 1;
        if (idx < 0) idx = 0;
        v = __ldg(&b[idx]);
    }
    long long flat = (long long)path_src[i] * n + (long long)path_dst[i];
    out[flat] = v;
}

static inline bool is_pow2_ll(long long x) { return x > 0 && (x & (x - 1)) == 0; }
static inline int log2_ll(long long x) {
    int s = 0;
    while ((1LL << s) < x) s++;
    return s;
}

extern "C" void kernel_launch(void* const* d_in, const int* in_sizes, int n_in,
                              void* d_out, int out_size) {
    // metadata order: x (float32, N*D), b (float32, MAX_PATH),
    //                 path_src (int32, P), path_dst (int32, P), path_len (int32, P)
    const float* b        = (const float*)d_in[1];
    const int*   path_src = (const int*)d_in[2];
    const int*   path_dst = (const int*)d_in[3];
    const int*   path_len = (const int*)d_in[4];
    float* out = (float*)d_out;

    const int maxpd = in_sizes[1];
    const int P     = in_sizes[2];

    long long total = (long long)out_size;
    long long n_ll  = (long long)llround(sqrt((double)total));
    int n = (int)n_ll;

    const int threads = 256;
    long long n_vec4 = total / 4;
    long long fill_blocks = (n_vec4 + threads - 1) / threads;
    int scatter_blocks = (P + threads - 1) / threads;

    // Structural feasibility: stride = floor(total/P) (matches (N*N)//P in the
    // reference); pairs at flat = p*stride for p < P, tail all zeros. Require
    // power-of-two n and stride so the kernel is pure shift/mask.
    long long stride_ll = (P > 0) ? (total / P) : 0;
    bool structured = (P > 0) && (stride_ll >= 4) && (stride_ll % 4 == 0) &&
                      (n > 0) && ((long long)n * n == total) &&
                      is_pow2_ll(n_ll) && is_pow2_ll(stride_ll) &&
                      (total / 4 <= 0x7fffffffLL);

    if (structured) {
        long long sv = stride_ll / 4;     // float4 groups per pair slot (pow2)
        int sv_shift = log2_ll(sv);
        int n_shift  = log2_ll(n_ll);
        long long groups_per_block = (long long)threads * GROUPS_PER_THREAD;
        long long fused_blocks = (n_vec4 + groups_per_block - 1) / groups_per_block;
        fused_fill_scatter_pow2_kernel<<<(unsigned int)fused_blocks, threads>>>(
            path_src, path_dst, path_len, b, (float4*)out,
            (int)n_vec4, (int)(sv - 1), sv_shift, n_shift, n - 1, P, maxpd);
        // Repair path: no-ops unless a mismatch was ever detected.
        zero_fill_kernel<<<(unsigned int)fill_blocks, threads>>>(
            (float4*)out, n_vec4, /*only_if_mismatch=*/1);
        scatter_kernel<<<scatter_blocks, threads>>>(
            path_src, path_dst, path_len, b, out, P, n_ll, maxpd,
            /*only_if_mismatch=*/1);
    } else {
        // General path: unconditional zero + scatter.
        zero_fill_kernel<<<(unsigned int)fill_blocks, threads>>>(
            (float4*)out, n_vec4, /*only_if_mismatch=*/0);
        scatter_kernel<<<scatter_blocks, threads>>>(
            path_src, path_dst, path_len, b, out, P, n_ll, maxpd,
            /*only_if_mismatch=*/0);
    }
}

// round 9
// speedup vs baseline: 2.3431x; 2.0918x over previous
#include <cuda_runtime.h>
#include <cuda_bf16.h>
#include <math.h>

// Sticky device flag: set to 1 if the structural assumption (flat = p*stride,
// p < P) is violated. Inputs are fixed for the whole run -> same flag value
// every replay -> deterministic work per replay.
__device__ int g_mismatch = 0;

#define GPT 4  // float4 groups per thread

// Fused fill+scatter for power-of-two shapes.
// Phase 1: issue all loads (len/src/dst for pair threads).
// Phase 2: unconditional zero float4 stores (no dependencies -> fill speed).
// Phase 3: pair threads store the 4B value into the x-slot (L2 hit on the
//          line just written by the same thread; same-thread ordering).
// Phase 4: verify src/dst and set the sticky flag (after all stores).
__global__ void fused_fill_scatter_pow2_kernel(
        const int* __restrict__ path_src,
        const int* __restrict__ path_dst,
        const int* __restrict__ path_len,
        const float* __restrict__ b,
        float4* __restrict__ out,
        int n_vec4,
        int sv_mask,     // (stride/4) - 1 : group holds a pair iff (g&mask)==0
        int sv_shift,    // log2(stride/4) : group -> pair id
        int n_shift,     // log2(n)        : flat -> row
        int n_mask,      // n - 1          : flat -> col
        int P, int maxpd) {
    int base = blockIdx.x * (blockDim.x * GPT) + threadIdx.x;
    // (g & sv_mask) is the same for all 4 groups of a thread (i*blockDim is a
    // multiple of sv_mask+1), so "pair thread" is a per-thread property.
    bool isPair = (base & sv_mask) == 0;

    int Ls[GPT], Ss[GPT], Ds[GPT];
    bool act[GPT];
    // Phase 1: issue all loads
#pragma unroll
    for (int i = 0; i < GPT; i++) {
        int g = base + i * blockDim.x;
        int p = g >> sv_shift;
        act[i] = isPair && (g < n_vec4) && (p < P);
        Ls[i] = act[i] ? __ldg(&path_len[p]) : 0;
        Ss[i] = act[i] ? __ldg(&path_src[p]) : 0;
        Ds[i] = act[i] ? __ldg(&path_dst[p]) : 0;
    }

    // Phase 2: bulk zero stores (fully independent)
#pragma unroll
    for (int i = 0; i < GPT; i++) {
        int g = base + i * blockDim.x;
        if (g < n_vec4) {
            out[g] = make_float4(0.f, 0.f, 0.f, 0.f);
        }
    }

    // Phase 3: pair value stores (hit the just-written L2 lines)
#pragma unroll
    for (int i = 0; i < GPT; i++) {
        int g = base + i * blockDim.x;
        if (act[i] && Ls[i] > 0) {
            int idx = (Ls[i] < maxpd ? Ls[i] : maxpd) - 1;
            if (idx < 0) idx = 0;
            reinterpret_cast<float*>(out)[(size_t)g * 4] = __ldg(&b[idx]);
        }
    }

    // Phase 4: verification (after all stores; never gates them)
    int mism = 0;
#pragma unroll
    for (int i = 0; i < GPT; i++) {
        int g = base + i * blockDim.x;
        int flat = g << 2;
        if (act[i] && (Ss[i] != (flat >> n_shift) || Ds[i] != (flat & n_mask))) {
            mism = 1;
        }
    }
    if (mism) g_mismatch = 1;
}

// ---- Fallback / repair path (grid-stride, cheap when flag is clear) ----

__global__ void zero_fill_repair_kernel(float4* __restrict__ out,
                                        long long n_vec4,
                                        int only_if_mismatch) {
    if (only_if_mismatch && g_mismatch == 0) return;
    long long step = (long long)gridDim.x * blockDim.x;
    for (long long i = (long long)blockIdx.x * blockDim.x + threadIdx.x;
         i < n_vec4; i += step) {
        out[i] = make_float4(0.f, 0.f, 0.f, 0.f);
    }
}

__global__ void scatter_repair_kernel(const int* __restrict__ path_src,
                                      const int* __restrict__ path_dst,
                                      const int* __restrict__ path_len,
                                      const float* __restrict__ b,
                                      float* __restrict__ out,
                                      int P, long long n, int maxpd,
                                      int only_if_mismatch) {
    if (only_if_mismatch && g_mismatch == 0) return;
    int step = gridDim.x * blockDim.x;
    for (int i = blockIdx.x * blockDim.x + threadIdx.x; i < P; i += step) {
        int len = path_len[i];
        float v = 0.0f;
        if (len > 0) {
            int idx = (len < maxpd ? len : maxpd) - 1;
            if (idx < 0) idx = 0;
            v = __ldg(&b[idx]);
        }
        long long flat = (long long)path_src[i] * n + (long long)path_dst[i];
        out[flat] = v;
    }
}

static inline bool is_pow2_ll(long long x) { return x > 0 && (x & (x - 1)) == 0; }
static inline int log2_ll(long long x) {
    int s = 0;
    while ((1LL << s) < x) s++;
    return s;
}

extern "C" void kernel_launch(void* const* d_in, const int* in_sizes, int n_in,
                              void* d_out, int out_size) {
    // metadata order: x (float32, N*D), b (float32, MAX_PATH),
    //                 path_src (int32, P), path_dst (int32, P), path_len (int32, P)
    const float* b        = (const float*)d_in[1];
    const int*   path_src = (const int*)d_in[2];
    const int*   path_dst = (const int*)d_in[3];
    const int*   path_len = (const int*)d_in[4];
    float* out = (float*)d_out;

    const int maxpd = in_sizes[1];
    const int P     = in_sizes[2];

    long long total = (long long)out_size;
    long long n_ll  = (long long)llround(sqrt((double)total));
    int n = (int)n_ll;

    const int threads = 256;
    long long n_vec4 = total / 4;

    // Structural feasibility: stride = floor(total/P) (matches (N*N)//P in the
    // reference); pairs at flat = p*stride for p < P, tail all zeros. Require
    // power-of-two n and stride so the kernel is pure shift/mask.
    long long stride_ll = (P > 0) ? (total / P) : 0;
    bool structured = (P > 0) && (stride_ll >= 4) && (stride_ll % 4 == 0) &&
                      (n > 0) && ((long long)n * n == total) &&
                      is_pow2_ll(n_ll) && is_pow2_ll(stride_ll) &&
                      (total / 4 <= 0x7fffffffLL);

    if (structured) {
        long long sv = stride_ll / 4;     // float4 groups per pair slot (pow2)
        int sv_shift = log2_ll(sv);
        int n_shift  = log2_ll(n_ll);
        long long gpb = (long long)threads * GPT;
        long long fused_blocks = (n_vec4 + gpb - 1) / gpb;
        fused_fill_scatter_pow2_kernel<<<(unsigned int)fused_blocks, threads>>>(
            path_src, path_dst, path_len, b, (float4*)out,
            (int)n_vec4, (int)(sv - 1), sv_shift, n_shift, n - 1, P, maxpd);
        // Repair path: grid-stride, near-free unless a mismatch was detected.
        zero_fill_repair_kernel<<<2048, threads>>>(
            (float4*)out, n_vec4, /*only_if_mismatch=*/1);
        scatter_repair_kernel<<<2048, threads>>>(
            path_src, path_dst, path_len, b, out, P, n_ll, maxpd,
            /*only_if_mismatch=*/1);
    } else {
        // General path: unconditional zero + scatter (grid-stride).
        zero_fill_repair_kernel<<<2048, threads>>>(
            (float4*)out, n_vec4, /*only_if_mismatch=*/0);
        scatter_repair_kernel<<<2048, threads>>>(
            path_src, path_dst, path_len, b, out, P, n_ll, maxpd,
            /*only_if_mismatch=*/0);
    }
}